// round 1
// baseline (speedup 1.0000x reference)
#include <cuda_runtime.h>

#define S   512
#define S2  (S*S)
#define NB  32
#define TX  32
#define TY  32
#define BLK 256

// Loss accumulators: [0]=sum|continuity|, [1]=sum|poisson|, [2]=bc loss
__device__ double g_acc[3];

__global__ void zero_kernel() {
    g_acc[0] = 0.0; g_acc[1] = 0.0; g_acc[2] = 0.0;
}

__global__ __launch_bounds__(BLK) void pde_kernel(const float* __restrict__ gen,
                                                  const float* __restrict__ pn) {
    // halo-2 tiles of the 4 fields (rows i0-2..i0+33, cols j0-2..j0+33)
    __shared__ float su[36][37], sv[36][37], sp[36][37], sq[36][37];
    // staged updated velocities: sun[r][cc] = u_new(i0+r, j0+cc-1), svn[rr][c] = v_new(i0+rr-1, j0+c)
    __shared__ float sun[32][34], svn[33][34];
    __shared__ float redC[8], redP[8];

    const int b  = blockIdx.z;
    const int i0 = 1 + blockIdx.y * TY;
    const int j0 = 1 + blockIdx.x * TX;
    const int tid = threadIdx.x;

    const float* u = gen + (size_t)b * 3 * S2;
    const float* v = u + S2;
    const float* p = v + S2;
    const float* q = pn + (size_t)b * S2;

    const float INV_DX  = 1.0f / 0.01f;
    const float INV_DT  = 1.0f / 0.001f;
    const float INV_DX2 = 1.0f / 0.0001f;
    const float DT      = 0.001f;

    // ---- Stage 1: load halo tiles (clamped; clamped values only feed invalid pad positions) ----
    for (int idx = tid; idx < 36 * 36; idx += BLK) {
        int r = idx / 36, c = idx % 36;
        int gy = i0 - 2 + r; gy = max(0, min(S - 1, gy));
        int gx = j0 - 2 + c; gx = max(0, min(S - 1, gx));
        int g = gy * S + gx;
        su[r][c] = u[g];
        sv[r][c] = v[g];
        sp[r][c] = p[g];
        sq[r][c] = q[g];
    }
    __syncthreads();

    // ---- Stage 2a: u_new at rows i0..i0+31, cols j0-1..j0+31  (K = VISC/DX = 1 exactly) ----
    for (int idx = tid; idx < 32 * 33; idx += BLK) {
        int r = idx / 33, cc = idx % 33;
        int i = i0 + r, j = j0 + cc - 1;
        int lr = r + 2, lc = cc + 1;          // su[lr][lc] == u[i][j]
        float un = su[lr][lc];
        if (i <= 510 && j >= 1 && j <= 509) {
            float ue1 = 0.5f * (su[lr][lc]   + su[lr][lc+1]);
            float fe1 = ue1 * ue1 - (su[lr][lc+1] - su[lr][lc]);
            float ue0 = 0.5f * (su[lr][lc-1] + su[lr][lc]);
            float fe0 = ue0 * ue0 - (su[lr][lc] - su[lr][lc-1]);
            float fn1 = 0.5f * (sv[lr][lc]   + sv[lr][lc+1])   * (0.5f * (su[lr][lc]   + su[lr+1][lc]))
                        - (su[lr+1][lc] - su[lr][lc]);
            float fn0 = 0.5f * (sv[lr-1][lc] + sv[lr-1][lc+1]) * (0.5f * (su[lr-1][lc] + su[lr][lc]))
                        - (su[lr][lc] - su[lr-1][lc]);
            float dudt = (-(fe1 - fe0) - (fn1 - fn0) - (sp[lr][lc+1] - sp[lr][lc])) * INV_DX;
            un += dudt * DT;
        }
        sun[r][cc] = un;
    }

    // ---- Stage 2b: v_new at rows i0-1..i0+31, cols j0..j0+31 ----
    for (int idx = tid; idx < 33 * 32; idx += BLK) {
        int rr = idx / 32, c = idx % 32;
        int i = i0 + rr - 1, j = j0 + c;
        int lr = rr + 1, lc = c + 2;          // sv[lr][lc] == v[i][j]
        float vn = sv[lr][lc];
        if (i >= 1 && i <= 509 && j <= 510) {
            float ge1 = 0.5f * (su[lr][lc]   + su[lr+1][lc])   * (0.5f * (sv[lr][lc]   + sv[lr][lc+1]))
                        - (sv[lr][lc+1] - sv[lr][lc]);
            float ge0 = 0.5f * (su[lr][lc-1] + su[lr+1][lc-1]) * (0.5f * (sv[lr][lc-1] + sv[lr][lc]))
                        - (sv[lr][lc] - sv[lr][lc-1]);
            float a1  = 0.5f * (sv[lr][lc]   + sv[lr+1][lc]);
            float gn1 = a1 * a1 - (sv[lr+1][lc] - sv[lr][lc]);
            float a0  = 0.5f * (sv[lr-1][lc] + sv[lr][lc]);
            float gn0 = a0 * a0 - (sv[lr][lc] - sv[lr-1][lc]);
            float dvdt = (-(ge1 - ge0) - (gn1 - gn0) - (sp[lr+1][lc] - sp[lr][lc])) * INV_DX;
            vn += dvdt * DT;
        }
        svn[rr][c] = vn;
    }
    __syncthreads();

    // ---- Stage 3: residuals at interior points ----
    float accC = 0.0f, accP = 0.0f;
    for (int idx = tid; idx < 32 * 32; idx += BLK) {
        int r = idx / 32, c = idx % 32;
        int i = i0 + r, j = j0 + c;
        if (i > 510 || j > 510) continue;
        int lr = r + 2, lc = c + 2;

        float cont = (su[lr][lc] - su[lr][lc-1] + sv[lr][lc] - sv[lr-1][lc]) * INV_DX;
        accC += fabsf(cont);

        float bconv = ((sun[r][c+1] - sun[r][c]) * INV_DX
                     + (svn[r+1][c] - svn[r][c]) * INV_DX) * INV_DT;

        float pp0 = sq[lr][lc]   - sp[lr][lc];
        float ppE = sq[lr][lc+1] - sp[lr][lc+1];
        float ppW = sq[lr][lc-1] - sp[lr][lc-1];
        float ppS = sq[lr+1][lc] - sp[lr+1][lc];
        float ppN = sq[lr-1][lc] - sp[lr-1][lc];
        float lap = 4.0f * pp0 - ppE - ppW - ppS - ppN;

        float pois = lap * INV_DX2 + bconv;
        accP += fabsf(pois);
    }

    // ---- Block reduction ----
    #pragma unroll
    for (int off = 16; off > 0; off >>= 1) {
        accC += __shfl_down_sync(0xFFFFFFFFu, accC, off);
        accP += __shfl_down_sync(0xFFFFFFFFu, accP, off);
    }
    int lane = tid & 31, w = tid >> 5;
    if (lane == 0) { redC[w] = accC; redP[w] = accP; }
    __syncthreads();
    if (w == 0) {
        float rc = (lane < 8) ? redC[lane] : 0.0f;
        float rp = (lane < 8) ? redP[lane] : 0.0f;
        #pragma unroll
        for (int off = 4; off > 0; off >>= 1) {
            rc += __shfl_down_sync(0xFFFFFFFFu, rc, off);
            rp += __shfl_down_sync(0xFFFFFFFFu, rp, off);
        }
        if (lane == 0) {
            atomicAdd(&g_acc[0], (double)rc);
            atomicAdd(&g_acc[1], (double)rp);
        }
    }
}

__global__ __launch_bounds__(512) void bc_kernel(const float* __restrict__ gen) {
    const int b = blockIdx.x;
    const int t = threadIdx.x;
    const float* u = gen + (size_t)b * 3 * S2;
    const float* v = u + S2;
    const float* p = v + S2;

    float s0 = 0.0f, s1 = 0.0f, s2 = 0.0f, s3 = 0.0f;
    // y0: rows 0/1 of u; row 0 of v,p
    if (t >= 1 && t <= 509) s0 += u[t] + u[S + t];
    if (t >= 1 && t <= 510) s0 += v[t] + p[t];
    // yL: rows 510/511 of u; row 511 of v,p
    if (t >= 1 && t <= 509) s1 += 2.0f - (u[510 * S + t] + u[511 * S + t]);
    if (t >= 1 && t <= 510) s1 += v[511 * S + t] + p[511 * S + t];
    // x0: cols 0/1 of v; col 0 of u,p
    if (t >= 1 && t <= 509) s2 += v[t * S] + v[t * S + 1];
    if (t >= 1 && t <= 510) s2 += u[t * S] + p[t * S];
    // xL: cols 511/510 of v; col 511 of u,p
    if (t >= 1 && t <= 509) s3 += v[t * S + 511] + v[t * S + 510];
    if (t >= 1 && t <= 510) s3 += u[t * S + 511] + p[t * S + 511];

    __shared__ float r0[16], r1[16], r2[16], r3[16];
    #pragma unroll
    for (int off = 16; off > 0; off >>= 1) {
        s0 += __shfl_down_sync(0xFFFFFFFFu, s0, off);
        s1 += __shfl_down_sync(0xFFFFFFFFu, s1, off);
        s2 += __shfl_down_sync(0xFFFFFFFFu, s2, off);
        s3 += __shfl_down_sync(0xFFFFFFFFu, s3, off);
    }
    int lane = t & 31, w = t >> 5;
    if (lane == 0) { r0[w] = s0; r1[w] = s1; r2[w] = s2; r3[w] = s3; }
    __syncthreads();
    if (t == 0) {
        float y0 = 0, yL = 0, x0 = 0, xL = 0;
        #pragma unroll
        for (int k = 0; k < 16; k++) { y0 += r0[k]; yL += r1[k]; x0 += r2[k]; xL += r3[k]; }
        atomicAdd(&g_acc[2], (double)(fabsf(y0) + fabsf(yL) + fabsf(x0) + fabsf(xL)));
    }
}

__global__ void fin_kernel(float* out) {
    double denom = (double)NB * 510.0 * 510.0;
    double r = 0.4 * (g_acc[0] / denom)
             + 0.2 * g_acc[2]
             + (1.0 - 0.4 - 0.2) * (g_acc[1] / denom);
    out[0] = (float)r;
}

extern "C" void kernel_launch(void* const* d_in, const int* in_sizes, int n_in,
                              void* d_out, int out_size) {
    const float* gen = (const float*)d_in[0];
    const float* pn  = (const float*)d_in[1];
    float* out = (float*)d_out;

    zero_kernel<<<1, 1>>>();
    dim3 grid((510 + TX - 1) / TX, (510 + TY - 1) / TY, NB);  // 16 x 16 x 32
    pde_kernel<<<grid, BLK>>>(gen, pn);
    bc_kernel<<<NB, 512>>>(gen);
    fin_kernel<<<1, 1>>>(out);
}

// round 2
// speedup vs baseline: 1.2166x; 1.2166x over previous
#include <cuda_runtime.h>

#define S  512
#define S2 (S*S)
#define NBATCH 32
#define NBLK_TOTAL 8192u

// Global accumulators (zero-initialized at module load; reset by finalize each run)
__device__ double g_acc[2] = {0.0, 0.0};            // [0]=sum|cont|, [1]=sum|pois|
__device__ double g_bc4[NBATCH * 4] = {0.0};        // per-batch per-edge signed sums
__device__ unsigned int g_count = 0u;

__global__ __launch_bounds__(256) void pil_kernel(const float* __restrict__ gen,
                                                  const float* __restrict__ pn,
                                                  float* __restrict__ out) {
    // halo tile: global rows i0-2..i0+32, cols j0-2..j0+32  (35x35), stride 36
    __shared__ float su[35][36], sv[35][36], sp[35][36], sq[35][36];
    __shared__ float redC[8], redP[8];
    __shared__ double dred[8];
    __shared__ unsigned int s_ticket;

    const int bx = blockIdx.x, by = blockIdx.y, b = blockIdx.z;
    const int i0 = 1 + by * 32;
    const int j0 = 1 + bx * 32;
    const int tid = threadIdx.x;
    const int tx = tid & 31, ty = tid >> 5;

    const float* u = gen + (size_t)b * 3 * S2;
    const float* v = u + S2;
    const float* p = v + S2;
    const float* q = pn + (size_t)b * S2;

    // ---- load halo tiles (clamped; clamped cells feed only guarded-out paths) ----
    for (int idx = tid; idx < 35 * 35; idx += 256) {
        int r = idx / 35, c = idx - r * 35;
        int gy = i0 - 2 + r; gy = max(0, min(S - 1, gy));
        int gx = j0 - 2 + c; gx = max(0, min(S - 1, gx));
        int g = gy * S + gx;
        su[r][c] = u[g];
        sv[r][c] = v[g];
        sp[r][c] = p[g];
        sq[r][c] = q[g];
    }
    __syncthreads();

    const int lc = tx + 2;            // local col of j
    const int j  = j0 + tx;
    const bool vj = (j <= 510);
    const int lr0 = ty * 4 + 2;       // local row of first output row

    float accC = 0.0f, accP = 0.0f;

    // u_new(i, jj) at local (lr, lcc). Identity outside 1<=jj<=509, i<=510.
    auto UNEW = [&](int lr, int lcc, int i_, int jj) -> float {
        float uc = su[lr][lcc];
        if (jj < 1 || jj > 509 || i_ > 510) return uc;
        float uw  = su[lr][lcc - 1], ue  = su[lr][lcc + 1];
        float un_ = su[lr - 1][lcc], us_ = su[lr + 1][lcc];
        float ax1 = 0.5f * (uc + ue); float fe1 = ax1 * ax1 - (ue - uc);
        float ax0 = 0.5f * (uw + uc); float fe0 = ax0 * ax0 - (uc - uw);
        float fn1 = 0.5f * (sv[lr][lcc] + sv[lr][lcc + 1]) * (0.5f * (uc + us_)) - (us_ - uc);
        float fn0 = 0.5f * (sv[lr - 1][lcc] + sv[lr - 1][lcc + 1]) * (0.5f * (un_ + uc)) - (uc - un_);
        float dudt = (-(fe1 - fe0) - (fn1 - fn0) - (sp[lr][lcc + 1] - sp[lr][lcc])) * 100.0f;
        return uc + dudt * 0.001f;
    };
    // v_new(ii, j) at local row lr. Identity outside 1<=ii<=509.
    auto VNEW = [&](int lr, int ii) -> float {
        float vc = sv[lr][lc];
        if (ii < 1 || ii > 509) return vc;
        float vn_ = sv[lr - 1][lc], vs_ = sv[lr + 1][lc];
        float vw  = sv[lr][lc - 1], ve  = sv[lr][lc + 1];
        float ge1 = 0.5f * (su[lr][lc] + su[lr + 1][lc]) * (0.5f * (vc + ve)) - (ve - vc);
        float ge0 = 0.5f * (su[lr][lc - 1] + su[lr + 1][lc - 1]) * (0.5f * (vw + vc)) - (vc - vw);
        float a1 = 0.5f * (vc + vs_); float gn1 = a1 * a1 - (vs_ - vc);
        float a0 = 0.5f * (vn_ + vc); float gn0 = a0 * a0 - (vc - vn_);
        float dvdt = (-(ge1 - ge0) - (gn1 - gn0) - (sp[lr + 1][lc] - sp[lr][lc])) * 100.0f;
        return vc + dvdt * 0.001f;
    };

    if (vj) {
        float vn_lo = VNEW(lr0 - 1, i0 + ty * 4 - 1);   // v_new(i-1, j) for k=0
        #pragma unroll
        for (int k = 0; k < 4; k++) {
            int lr = lr0 + k;
            int i  = i0 + ty * 4 + k;
            float vn_hi = VNEW(lr, i);
            if (i <= 510) {
                float un1 = UNEW(lr, lc,     i, j);
                float un0 = UNEW(lr, lc - 1, i, j - 1);
                float cont = (su[lr][lc] - su[lr][lc - 1] + sv[lr][lc] - sv[lr - 1][lc]) * 100.0f;
                float bconv = ((un1 - un0) + (vn_hi - vn_lo)) * 100000.0f;
                float pp0 = sq[lr][lc] - sp[lr][lc];
                float lap = 4.0f * pp0
                          - (sq[lr][lc + 1] - sp[lr][lc + 1])
                          - (sq[lr][lc - 1] - sp[lr][lc - 1])
                          - (sq[lr + 1][lc] - sp[lr + 1][lc])
                          - (sq[lr - 1][lc] - sp[lr - 1][lc]);
                accC += fabsf(cont);
                accP += fabsf(lap * 10000.0f + bconv);
            }
            vn_lo = vn_hi;
        }
    }

    // ---- boundary-condition edge sums (edge blocks only, from already-loaded smem) ----
    {
        float es = 0.0f; int eidx = -1;
        if (tid < 32) {
            int jj = j0 + tid, lcc = tid + 2;
            if (by == 0) {                           // rows 0,1  (y0)
                eidx = 0;
                if (jj <= 509) es += su[1][lcc] + su[2][lcc];
                if (jj <= 510) es += sv[1][lcc] + sp[1][lcc];
            } else if (by == 15) {                   // rows 510,511 (yL)
                eidx = 1;
                if (jj <= 509) es += 2.0f - (su[31][lcc] + su[32][lcc]);
                if (jj <= 510) es += sv[32][lcc] + sp[32][lcc];
            }
        } else if (tid < 64) {
            int lane = tid - 32;
            int ii = i0 + lane, lrr = lane + 2;
            if (bx == 0) {                           // cols 0,1  (x0)
                eidx = 2;
                if (ii <= 509) es += sv[lrr][1] + sv[lrr][2];
                if (ii <= 510) es += su[lrr][1] + sp[lrr][1];
            } else if (bx == 15) {                   // cols 510,511 (xL)
                eidx = 3;
                if (ii <= 509) es += sv[lrr][32] + sv[lrr][31];
                if (ii <= 510) es += su[lrr][32] + sp[lrr][32];
            }
        }
        if (eidx >= 0) {                             // warp-uniform branch
            #pragma unroll
            for (int off = 16; off > 0; off >>= 1)
                es += __shfl_down_sync(0xFFFFFFFFu, es, off);
            if ((tid & 31) == 0)
                atomicAdd(&g_bc4[b * 4 + eidx], (double)es);
        }
    }

    // ---- block reduction of residual sums ----
    #pragma unroll
    for (int off = 16; off > 0; off >>= 1) {
        accC += __shfl_down_sync(0xFFFFFFFFu, accC, off);
        accP += __shfl_down_sync(0xFFFFFFFFu, accP, off);
    }
    if ((tid & 31) == 0) { redC[ty] = accC; redP[ty] = accP; }
    __syncthreads();
    if (ty == 0) {
        float rc = (tx < 8) ? redC[tx] : 0.0f;
        float rp = (tx < 8) ? redP[tx] : 0.0f;
        #pragma unroll
        for (int off = 4; off > 0; off >>= 1) {
            rc += __shfl_down_sync(0xFFFFFFFFu, rc, off);
            rp += __shfl_down_sync(0xFFFFFFFFu, rp, off);
        }
        if (tx == 0) {
            atomicAdd(&g_acc[0], (double)rc);
            atomicAdd(&g_acc[1], (double)rp);
        }
    }

    // ---- last-block finalize (threadFenceReduction pattern) ----
    __threadfence();
    if (tid == 0) s_ticket = atomicAdd(&g_count, 1u);
    __syncthreads();
    if (s_ticket == NBLK_TOTAL - 1u) {
        double mybc = 0.0;
        if (tid < NBATCH * 4)
            mybc = fabs(atomicAdd(&g_bc4[tid], 0.0));   // coherent L2 read
        #pragma unroll
        for (int off = 16; off > 0; off >>= 1)
            mybc += __shfl_down_sync(0xFFFFFFFFu, mybc, off);
        if ((tid & 31) == 0) dred[ty] = mybc;
        __syncthreads();
        if (tid == 0) {
            double bc = 0.0;
            #pragma unroll
            for (int k = 0; k < 8; k++) bc += dred[k];
            double C = atomicAdd(&g_acc[0], 0.0);
            double P = atomicAdd(&g_acc[1], 0.0);
            double denom = 32.0 * 510.0 * 510.0;
            out[0] = (float)(0.4 * (C / denom) + 0.2 * bc + (1.0 - 0.4 - 0.2) * (P / denom));
            g_acc[0] = 0.0; g_acc[1] = 0.0;
        }
        if (tid < NBATCH * 4) g_bc4[tid] = 0.0;
        __threadfence();
        __syncthreads();
        if (tid == 0) g_count = 0u;
    }
}

extern "C" void kernel_launch(void* const* d_in, const int* in_sizes, int n_in,
                              void* d_out, int out_size) {
    const float* gen = (const float*)d_in[0];
    const float* pn  = (const float*)d_in[1];
    float* out = (float*)d_out;
    dim3 grid(16, 16, NBATCH);   // 16 x 16 x 32 = 8192 blocks
    pil_kernel<<<grid, 256>>>(gen, pn, out);
}